// round 14
// baseline (speedup 1.0000x reference)
#include <cuda_runtime.h>
#include <cuda_fp16.h>
#include <math.h>
#include <stdint.h>
#include <type_traits>

// Problem constants
#define B_ 2
#define S_ 2048
#define D_ 1024
#define H_ 16
#define DK_ 64

// ---------------- scratch (no cudaMalloc allowed) ----------------
__device__ __half g_qh[(size_t)B_ * S_ * D_];
__device__ __half g_kh[(size_t)B_ * S_ * D_];
__device__ __half g_vh[(size_t)B_ * S_ * D_];
__device__ __half g_ctxh[(size_t)B_ * S_ * D_];
// fp16 copies of inputs / weights
__device__ __half g_xq[(size_t)B_ * S_ * D_];
__device__ __half g_xk[(size_t)B_ * S_ * D_];
__device__ __half g_xv[(size_t)B_ * S_ * D_];
__device__ __half g_wq[(size_t)D_ * D_];
__device__ __half g_wk[(size_t)D_ * D_];
__device__ __half g_wv[(size_t)D_ * D_];
__device__ __half g_wo[(size_t)D_ * D_];
// fp16 exp(scores) scratch
__device__ __half g_ph[(size_t)B_ * H_ * S_ * S_];
// per-row exp partial sums: [z][row][16 bn-tiles * 4 wn] = 64 partials/row
__device__ float g_partial[(size_t)B_ * H_ * S_ * 64];

// ---------------- FP16 helpers ----------------
__device__ __forceinline__ uint32_t f2h2(float lo, float hi) {
    __half2 h = __floats2half2_rn(lo, hi);
    return *(uint32_t*)&h;
}

__device__ __forceinline__ void mma_f16(float c[4],
    uint32_t a0, uint32_t a1, uint32_t a2, uint32_t a3,
    uint32_t b0, uint32_t b1)
{
    asm volatile(
        "mma.sync.aligned.m16n8k16.row.col.f32.f16.f16.f32 "
        "{%0,%1,%2,%3}, {%4,%5,%6,%7}, {%8,%9}, {%0,%1,%2,%3};"
        : "+f"(c[0]), "+f"(c[1]), "+f"(c[2]), "+f"(c[3])
        : "r"(a0), "r"(a1), "r"(a2), "r"(a3), "r"(b0), "r"(b1));
}

#define STS8HU(s, kkb, r, u) do { \
    (s)[(kkb) + 0][r] = (u).x; \
    (s)[(kkb) + 1][r] = (u).y; \
    (s)[(kkb) + 2][r] = (u).z; \
    (s)[(kkb) + 3][r] = (u).w; \
} while (0)

// ---------------- cp.async helpers ----------------
#define CP_ASYNC16(saddr, gptr) \
    asm volatile("cp.async.cg.shared.global [%0], [%1], 16;" \
                 :: "r"(saddr), "l"(gptr) : "memory")
#define CP_COMMIT() asm volatile("cp.async.commit_group;" ::: "memory")
#define CP_WAIT1()  asm volatile("cp.async.wait_group 1;" ::: "memory")

// ================= fp32 -> fp16 conversion (inputs + weights) =================
__global__ __launch_bounds__(256) void to_half7(
    const float* __restrict__ s0, const float* __restrict__ s1, const float* __restrict__ s2,
    const float* __restrict__ s3, const float* __restrict__ s4, const float* __restrict__ s5,
    const float* __restrict__ s6,
    __half* __restrict__ d0, __half* __restrict__ d1, __half* __restrict__ d2,
    __half* __restrict__ d3, __half* __restrict__ d4, __half* __restrict__ d5,
    __half* __restrict__ d6)
{
    int b = blockIdx.x;
    const float* src; __half* dst; int off;
    if      (b < 2048) { src = s0; dst = d0; off = b; }
    else if (b < 4096) { src = s1; dst = d1; off = b - 2048; }
    else if (b < 6144) { src = s2; dst = d2; off = b - 4096; }
    else {
        int w = (b - 6144) >> 9;
        off = (b - 6144) & 511;
        src = (w == 0) ? s3 : (w == 1) ? s4 : (w == 2) ? s5 : s6;
        dst = (w == 0) ? d3 : (w == 1) ? d4 : (w == 2) ? d5 : d6;
    }
    size_t base = (size_t)off * 2048 + threadIdx.x * 8;
    float4 u0 = *(const float4*)(src + base);
    float4 u1 = *(const float4*)(src + base + 4);
    uint4 o;
    o.x = f2h2(u0.x, u0.y); o.y = f2h2(u0.z, u0.w);
    o.z = f2h2(u1.x, u1.y); o.w = f2h2(u1.z, u1.w);
    *(uint4*)(dst + base) = o;
}

// ============ core fp16 NT GEMM mainloop — cp.async 3-stage ============
// smem layout per stage: [128 rows][12 words] (word = 2 fp16 along k, 8 used + pad 4).
template<int KDIM>
__device__ __forceinline__ void gemm_core_cp(
    const __half* __restrict__ Ag, const __half* __restrict__ Bg,
    uint32_t* __restrict__ As, uint32_t* __restrict__ Bs,
    int tid, int lane, int wm, int wn, float acc[4][4][4])
{
    const int arow = tid >> 1;
    const int kk4  = (tid & 1) * 4;
    const uint32_t a_sm = (uint32_t)__cvta_generic_to_shared(As) + (uint32_t)(arow * 48 + kk4 * 4);
    const uint32_t b_sm = (uint32_t)__cvta_generic_to_shared(Bs) + (uint32_t)(arow * 48 + kk4 * 4);
    const int NIT = KDIM / 16;

#pragma unroll
    for (int s = 0; s < 2; s++) {
        if (s < NIT) {
            CP_ASYNC16(a_sm + s * (128 * 48), Ag + s * 16);
            CP_ASYNC16(b_sm + s * (128 * 48), Bg + s * 16);
        }
        CP_COMMIT();
    }

    const int mg = wm * 64 + (lane >> 2);
    const int ng = wn * 32 + (lane >> 2);
    const int kl = lane & 3;

    int stage = 0;
    for (int it = 0; it < NIT; it++) {
        CP_WAIT1();
        __syncthreads();
        {
            int s2 = stage + 2; if (s2 >= 3) s2 -= 3;
            if (it + 2 < NIT) {
                CP_ASYNC16(a_sm + s2 * (128 * 48), Ag + (it + 2) * 16);
                CP_ASYNC16(b_sm + s2 * (128 * 48), Bg + (it + 2) * 16);
            }
            CP_COMMIT();
        }
        const uint32_t* Asb = As + stage * (128 * 12);
        const uint32_t* Bsb = Bs + stage * (128 * 12);
        uint32_t af[4][4];
#pragma unroll
        for (int i = 0; i < 4; i++) {
            af[i][0] = Asb[(mg + i * 16) * 12 + kl];
            af[i][1] = Asb[(mg + i * 16 + 8) * 12 + kl];
            af[i][2] = Asb[(mg + i * 16) * 12 + kl + 4];
            af[i][3] = Asb[(mg + i * 16 + 8) * 12 + kl + 4];
        }
        uint32_t bf[4][2];
#pragma unroll
        for (int j = 0; j < 4; j++) {
            bf[j][0] = Bsb[(ng + j * 8) * 12 + kl];
            bf[j][1] = Bsb[(ng + j * 8) * 12 + kl + 4];
        }
#pragma unroll
        for (int j = 0; j < 4; j++)
#pragma unroll
            for (int i = 0; i < 4; i++)
                mma_f16(acc[i][j], af[i][0], af[i][1], af[i][2], af[i][3],
                        bf[j][0], bf[j][1]);

        stage++; if (stage == 3) stage = 0;
    }
}

// ================= fused q/k/v projections =================
template<class TC>
__global__ __launch_bounds__(256, 2) void proj3_h(
    const __half* __restrict__ X0, const __half* __restrict__ X1, const __half* __restrict__ X2,
    const __half* __restrict__ W0, const __half* __restrict__ W1, const __half* __restrict__ W2,
    const float* __restrict__ bi0, const float* __restrict__ bi1, const float* __restrict__ bi2,
    TC* __restrict__ C0, TC* __restrict__ C1, TC* __restrict__ C2)
{
    constexpr bool OUT_HALF = std::is_same<TC, __half>::value;
    __shared__ __align__(16) uint32_t As[3 * 128 * 12];
    __shared__ __align__(16) uint32_t Bs[3 * 128 * 12];

    const int tid  = threadIdx.x;
    const int lane = tid & 31;
    const int wid  = tid >> 5;
    const int wm   = wid & 1;
    const int wn   = wid >> 1;
    const int bm   = blockIdx.y * 128;
    const int bn   = blockIdx.x * 128;
    const int z    = blockIdx.z;

    const __half* X    = (z == 0) ? X0 : (z == 1) ? X1 : X2;
    const __half* W    = (z == 0) ? W0 : (z == 1) ? W1 : W2;
    const float*  bias = (z == 0) ? bi0 : (z == 1) ? bi1 : bi2;
    TC*           C    = (z == 0) ? C0 : (z == 1) ? C1 : C2;

    const int arow = tid >> 1;
    const int ak   = (tid & 1) * 8;
    const __half* Ap = X + (size_t)(bm + arow) * D_ + ak;
    const __half* Bp = W + (size_t)(bn + arow) * D_ + ak;

    float acc[4][4][4];
#pragma unroll
    for (int i = 0; i < 4; i++)
#pragma unroll
        for (int j = 0; j < 4; j++)
#pragma unroll
            for (int e = 0; e < 4; e++) acc[i][j][e] = 0.f;

    gemm_core_cp<D_>(Ap, Bp, As, Bs, tid, lane, wm, wn, acc);

    const int rl   = wm * 64 + (lane >> 2);
    const int col0 = bn + wn * 32 + (lane & 3) * 2;
    float2 bvj[4];
#pragma unroll
    for (int j = 0; j < 4; j++)
        bvj[j] = *(const float2*)&bias[col0 + j * 8];

#pragma unroll
    for (int i = 0; i < 4; i++) {
#pragma unroll
        for (int j = 0; j < 4; j++) {
            const int r = bm + rl + i * 16;
            const int c = col0 + j * 8;
            float lx = acc[i][j][0] + bvj[j].x, ly = acc[i][j][1] + bvj[j].y;
            float hx = acc[i][j][2] + bvj[j].x, hy = acc[i][j][3] + bvj[j].y;
            if constexpr (OUT_HALF) {
                *(uint32_t*)&C[(size_t)r * D_ + c]       = f2h2(lx, ly);
                *(uint32_t*)&C[(size_t)(r + 8) * D_ + c] = f2h2(hx, hy);
            } else {
                float2 lo; lo.x = lx; lo.y = ly;
                float2 hi; hi.x = hx; hi.y = hy;
                *(float2*)&C[(size_t)r * D_ + c]       = lo;
                *(float2*)&C[(size_t)(r + 8) * D_ + c] = hi;
            }
        }
    }
}

// ================= QK^T -> exp fp16 scratch + partials =================
__global__ __launch_bounds__(256, 2) void qk_h(
    const __half* __restrict__ Q, const __half* __restrict__ K,
    __half* __restrict__ Pexp, float* __restrict__ partial)
{
    __shared__ __align__(16) uint32_t As[3 * 128 * 12];
    __shared__ __align__(16) uint32_t Bs[3 * 128 * 12];

    const int tid  = threadIdx.x;
    const int lane = tid & 31;
    const int wid  = tid >> 5;
    const int wm   = wid & 1;
    const int wn   = wid >> 1;
    const int bm   = blockIdx.y * 128;
    const int bn   = blockIdx.x * 128;
    const int z    = blockIdx.z;
    const int zb   = z >> 4, zh = z & 15;
    const size_t base = (size_t)zb * S_ * D_ + (size_t)zh * DK_;

    const int arow = tid >> 1;
    const int ak   = (tid & 1) * 8;
    const __half* Ap = Q + base + (size_t)(bm + arow) * D_ + ak;
    const __half* Bp = K + base + (size_t)(bn + arow) * D_ + ak;

    float acc[4][4][4];
#pragma unroll
    for (int i = 0; i < 4; i++)
#pragma unroll
        for (int j = 0; j < 4; j++)
#pragma unroll
            for (int e = 0; e < 4; e++) acc[i][j][e] = 0.f;

    gemm_core_cp<DK_>(Ap, Bp, As, Bs, tid, lane, wm, wn, acc);

    __half* Cp = Pexp + (size_t)z * S_ * S_;
    const int rl   = wm * 64 + (lane >> 2);
    const int col0 = bn + wn * 32 + (lane & 3) * 2;

#pragma unroll
    for (int i = 0; i < 4; i++) {
        const int rlo = bm + rl + i * 16;
        const int rhi = rlo + 8;
        float pl = 0.f, ph = 0.f;
#pragma unroll
        for (int j = 0; j < 4; j++) {
            float e0 = __expf(acc[i][j][0] * 0.125f);
            float e1 = __expf(acc[i][j][1] * 0.125f);
            float e2 = __expf(acc[i][j][2] * 0.125f);
            float e3 = __expf(acc[i][j][3] * 0.125f);
            *(uint32_t*)&Cp[(size_t)rlo * S_ + col0 + j * 8] = f2h2(e0, e1);
            *(uint32_t*)&Cp[(size_t)rhi * S_ + col0 + j * 8] = f2h2(e2, e3);
            pl += e0 + e1;
            ph += e2 + e3;
        }
        pl += __shfl_xor_sync(0xffffffffu, pl, 1);
        pl += __shfl_xor_sync(0xffffffffu, pl, 2);
        ph += __shfl_xor_sync(0xffffffffu, ph, 1);
        ph += __shfl_xor_sync(0xffffffffu, ph, 2);
        if ((lane & 3) == 0) {
            partial[((size_t)z * S_ + rlo) * 64 + blockIdx.x * 4 + wn] = pl;
            partial[((size_t)z * S_ + rhi) * 64 + blockIdx.x * 4 + wn] = ph;
        }
    }
}

// ================= PV: cp.async-pipelined P + depth-2 V prefetch =================
// P smem per stage: [128 rows][12 words] (8 used = 16 halves). 3 stages.
// attn fp32 write reads P back from smem (same bytes -> identical numerics).
__global__ __launch_bounds__(256, 2) void pv_h(
    const __half* __restrict__ Pexp, float* __restrict__ attn,
    const __half* __restrict__ Vg,
    __half* __restrict__ ctx, const float* __restrict__ partial)
{
    __shared__ __align__(16) uint32_t Psr[3 * 128 * 12];
    __shared__ uint32_t Vs[2][8][72];
    __shared__ float s_inv[128];

    const int tid  = threadIdx.x;
    const int lane = tid & 31;
    const int wid  = tid >> 5;
    const int wm   = wid & 3;
    const int wn   = wid >> 2;
    const int bm   = blockIdx.x * 128;
    const int z    = blockIdx.y;
    const int zb   = z >> 4, zh = z & 15;

    // prologue: per-row inverse sums (64 partials per row)
    {
        const int r = tid >> 1;
        const float* pp = partial + ((size_t)z * S_ + bm + r) * 64 + (tid & 1) * 32;
        float s = 0.f;
#pragma unroll
        for (int f = 0; f < 8; f++) {
            float4 u = ((const float4*)pp)[f];
            s += (u.x + u.y) + (u.z + u.w);
        }
        s += __shfl_xor_sync(0xffffffffu, s, 1);
        if (!(tid & 1)) s_inv[r] = 1.f / s;
    }
    __syncthreads();

    const int prow = tid >> 1;
    const int pk4  = (tid & 1) * 4;    // word offset within the 12-word row
    const __half* Pg = Pexp + (size_t)z * S_ * S_ + (size_t)(bm + prow) * S_ + (tid & 1) * 8;
    float* Aout = attn + (size_t)z * S_ * S_ + (size_t)(bm + prow) * S_ + (tid & 1) * 8;
    const float inv = s_inv[prow];
    const uint32_t p_sm = (uint32_t)__cvta_generic_to_shared(Psr)
                        + (uint32_t)(prow * 48 + pk4 * 4);

    const int vu = wid;
    const int vn = lane * 2;
    const __half* Vbase = Vg + (size_t)zb * S_ * D_ + (size_t)zh * DK_ + vn;

    float acc[2][4][4];
#pragma unroll
    for (int i = 0; i < 2; i++)
#pragma unroll
        for (int j = 0; j < 4; j++)
#pragma unroll
            for (int e = 0; e < 4; e++) acc[i][j][e] = 0.f;

    const int NIT = S_ / 16;

    // V stage 0 STS
    {
        __half2 e0 = *(const __half2*)(Vbase + (size_t)(2 * vu) * D_);
        __half2 e1 = *(const __half2*)(Vbase + (size_t)(2 * vu + 1) * D_);
        __half2 w0 = __lows2half2(e0, e1);
        __half2 w1 = __highs2half2(e0, e1);
        Vs[0][vu][vn]     = *(uint32_t*)&w0;
        Vs[0][vu][vn + 1] = *(uint32_t*)&w1;
    }
    // V regs for it=1
    __half2 veA, voA, veB, voB;
    veA = *(const __half2*)(Vbase + (size_t)(16 + 2 * vu) * D_);
    voA = *(const __half2*)(Vbase + (size_t)(16 + 2 * vu + 1) * D_);

    // P cp.async stages 0,1
#pragma unroll
    for (int s = 0; s < 2; s++) {
        CP_ASYNC16(p_sm + s * (128 * 48), Pg + s * 16);
        CP_COMMIT();
    }

    const int mg = wm * 32 + (lane >> 2);
    const int ng = wn * 32 + (lane >> 2);
    const int kl = lane & 3;

    int stage = 0;
    for (int it = 0; it < NIT; it++) {
        const int cur = it & 1;
        CP_WAIT1();
        __syncthreads();
        // issue P stage it+2
        {
            int s2 = stage + 2; if (s2 >= 3) s2 -= 3;
            if (it + 2 < NIT) CP_ASYNC16(p_sm + s2 * (128 * 48), Pg + (it + 2) * 16);
            CP_COMMIT();
        }
        // V regs for it+2
        if (it + 2 < NIT) {
            const int k0 = (it + 2) * 16;
            veB = *(const __half2*)(Vbase + (size_t)(k0 + 2 * vu) * D_);
            voB = *(const __half2*)(Vbase + (size_t)(k0 + 2 * vu + 1) * D_);
        }

        const uint32_t* Pb = Psr + stage * (128 * 12);
        // compute
        {
            uint32_t af[2][4];
#pragma unroll
            for (int i = 0; i < 2; i++) {
                af[i][0] = Pb[(mg + i * 16) * 12 + kl];
                af[i][1] = Pb[(mg + i * 16 + 8) * 12 + kl];
                af[i][2] = Pb[(mg + i * 16) * 12 + kl + 4];
                af[i][3] = Pb[(mg + i * 16 + 8) * 12 + kl + 4];
            }
            uint32_t bf[4][2];
#pragma unroll
            for (int j = 0; j < 4; j++) {
                bf[j][0] = Vs[cur][kl    ][ng + j * 8];
                bf[j][1] = Vs[cur][kl + 4][ng + j * 8];
            }
#pragma unroll
            for (int j = 0; j < 4; j++)
#pragma unroll
                for (int i = 0; i < 2; i++)
                    mma_f16(acc[i][j], af[i][0], af[i][1], af[i][2], af[i][3],
                            bf[j][0], bf[j][1]);
        }
        // attn write for this tile: read P back from smem, scale, store fp32
        {
            uint4 pw = *(const uint4*)&Pb[prow * 12 + pk4];
            __half2 h0 = *(__half2*)&pw.x, h1 = *(__half2*)&pw.y;
            __half2 h2 = *(__half2*)&pw.z, h3 = *(__half2*)&pw.w;
            float4 o0, o1;
            o0.x = __low2float(h0) * inv;  o0.y = __high2float(h0) * inv;
            o0.z = __low2float(h1) * inv;  o0.w = __high2float(h1) * inv;
            o1.x = __low2float(h2) * inv;  o1.y = __high2float(h2) * inv;
            o1.z = __low2float(h3) * inv;  o1.w = __high2float(h3) * inv;
            *(float4*)(Aout + it * 16)     = o0;
            *(float4*)(Aout + it * 16 + 4) = o1;
        }
        // V STS for it+1 (buffer cur^1; safe: compute(it-1) done at top sync)
        if (it + 1 < NIT) {
            __half2 w0 = __lows2half2(veA, voA);
            __half2 w1 = __highs2half2(veA, voA);
            Vs[cur ^ 1][vu][vn]     = *(uint32_t*)&w0;
            Vs[cur ^ 1][vu][vn + 1] = *(uint32_t*)&w1;
        }
        veA = veB; voA = voB;
        stage++; if (stage == 3) stage = 0;
    }

    __half* Cc = ctx + (size_t)zb * S_ * D_ + (size_t)zh * DK_;
    const int row0 = bm + wm * 32 + (lane >> 2);
    const int col0 = wn * 32 + (lane & 3) * 2;
#pragma unroll
    for (int i = 0; i < 2; i++) {
        const float ilo = s_inv[wm * 32 + (lane >> 2) + i * 16];
        const float ihi = s_inv[wm * 32 + (lane >> 2) + i * 16 + 8];
#pragma unroll
        for (int j = 0; j < 4; j++) {
            const int r = row0 + i * 16;
            const int c = col0 + j * 8;
            *(uint32_t*)&Cc[(size_t)r * D_ + c]       = f2h2(acc[i][j][0] * ilo, acc[i][j][1] * ilo);
            *(uint32_t*)&Cc[(size_t)(r + 8) * D_ + c] = f2h2(acc[i][j][2] * ihi, acc[i][j][3] * ihi);
        }
    }
}

// ---------------- launch ----------------
extern "C" void kernel_launch(void* const* d_in, const int* in_sizes, int n_in,
                              void* d_out, int out_size)
{
    const float* query = (const float*)d_in[0];
    const float* key   = (const float*)d_in[1];
    const float* value = (const float*)d_in[2];
    const float* Wq    = (const float*)d_in[3];
    const float* bq    = (const float*)d_in[4];
    const float* Wk    = (const float*)d_in[5];
    const float* bk    = (const float*)d_in[6];
    const float* Wv    = (const float*)d_in[7];
    const float* bv    = (const float*)d_in[8];
    const float* Wo    = (const float*)d_in[9];
    const float* bo    = (const float*)d_in[10];

    float* out  = (float*)d_out;                          // (B,S,D)
    float* attn = out + (size_t)B_ * S_ * D_;             // (B,H,S,S)

    __half *qh, *kh, *vh, *ctxh, *xq, *xk, *xv, *wq, *wk, *wv, *wo, *ph;
    float *part;
    cudaGetSymbolAddress((void**)&qh,   g_qh);
    cudaGetSymbolAddress((void**)&kh,   g_kh);
    cudaGetSymbolAddress((void**)&vh,   g_vh);
    cudaGetSymbolAddress((void**)&ctxh, g_ctxh);
    cudaGetSymbolAddress((void**)&xq,   g_xq);
    cudaGetSymbolAddress((void**)&xk,   g_xk);
    cudaGetSymbolAddress((void**)&xv,   g_xv);
    cudaGetSymbolAddress((void**)&wq,   g_wq);
    cudaGetSymbolAddress((void**)&wk,   g_wk);
    cudaGetSymbolAddress((void**)&wv,   g_wv);
    cudaGetSymbolAddress((void**)&wo,   g_wo);
    cudaGetSymbolAddress((void**)&ph,   g_ph);
    cudaGetSymbolAddress((void**)&part, g_partial);

    // 0) convert inputs + weights to fp16 once
    to_half7<<<8192, 256>>>(query, key, value, Wq, Wk, Wv, Wo,
                            xq, xk, xv, wq, wk, wv, wo);

    // 1) fused q/k/v projections (grid.z = 3)
    dim3 pgrid(D_ / 128, (B_ * S_) / 128, 3);
    proj3_h<__half><<<pgrid, 256>>>(xq, xk, xv, wq, wk, wv, bq, bk, bv, qh, kh, vh);

    // 2) QK^T -> exp fp16 scratch + partials
    dim3 qkgrid(S_ / 128, S_ / 128, B_ * H_);
    qk_h<<<qkgrid, 256>>>(qh, kh, ph, part);

    // 3) normalized attn write + ctx = inv * (expP @ V)
    dim3 pvgrid(S_ / 128, B_ * H_);
    pv_h<<<pvgrid, 256>>>(ph, attn, vh, ctxh, part);

    // 4) output projection (fp16 x fp16 -> fp32)
    dim3 ogrid(D_ / 128, (B_ * S_) / 128, 1);
    proj3_h<float><<<ogrid, 256>>>(ctxh, ctxh, ctxh, wo, wo, wo, bo, bo, bo, out, out, out);
}

// round 15
// speedup vs baseline: 1.0091x; 1.0091x over previous
#include <cuda_runtime.h>
#include <cuda_fp16.h>
#include <math.h>
#include <stdint.h>
#include <type_traits>

// Problem constants
#define B_ 2
#define S_ 2048
#define D_ 1024
#define H_ 16
#define DK_ 64

// ---------------- scratch (no cudaMalloc allowed) ----------------
__device__ __half g_qh[(size_t)B_ * S_ * D_];
__device__ __half g_kh[(size_t)B_ * S_ * D_];
__device__ __half g_vh[(size_t)B_ * S_ * D_];
__device__ __half g_ctxh[(size_t)B_ * S_ * D_];
// fp16 copies of inputs / weights
__device__ __half g_xq[(size_t)B_ * S_ * D_];
__device__ __half g_xk[(size_t)B_ * S_ * D_];
__device__ __half g_xv[(size_t)B_ * S_ * D_];
__device__ __half g_wq[(size_t)D_ * D_];
__device__ __half g_wk[(size_t)D_ * D_];
__device__ __half g_wv[(size_t)D_ * D_];
__device__ __half g_wo[(size_t)D_ * D_];
// fp16 exp(scores) scratch
__device__ __half g_ph[(size_t)B_ * H_ * S_ * S_];
// per-row exp partial sums: [z][row][16 bn-tiles * 4 wn] = 64 partials/row
__device__ float g_partial[(size_t)B_ * H_ * S_ * 64];

// ---------------- FP16 helpers ----------------
__device__ __forceinline__ uint32_t f2h2(float lo, float hi) {
    __half2 h = __floats2half2_rn(lo, hi);
    return *(uint32_t*)&h;
}

__device__ __forceinline__ void mma_f16(float c[4],
    uint32_t a0, uint32_t a1, uint32_t a2, uint32_t a3,
    uint32_t b0, uint32_t b1)
{
    asm volatile(
        "mma.sync.aligned.m16n8k16.row.col.f32.f16.f16.f32 "
        "{%0,%1,%2,%3}, {%4,%5,%6,%7}, {%8,%9}, {%0,%1,%2,%3};"
        : "+f"(c[0]), "+f"(c[1]), "+f"(c[2]), "+f"(c[3])
        : "r"(a0), "r"(a1), "r"(a2), "r"(a3), "r"(b0), "r"(b1));
}

#define STS8HU(s, kkb, r, u) do { \
    (s)[(kkb) + 0][r] = (u).x; \
    (s)[(kkb) + 1][r] = (u).y; \
    (s)[(kkb) + 2][r] = (u).z; \
    (s)[(kkb) + 3][r] = (u).w; \
} while (0)

// ---------------- cp.async helpers ----------------
#define CP_ASYNC16(saddr, gptr) \
    asm volatile("cp.async.cg.shared.global [%0], [%1], 16;" \
                 :: "r"(saddr), "l"(gptr) : "memory")
#define CP_COMMIT() asm volatile("cp.async.commit_group;" ::: "memory")
#define CP_WAIT1()  asm volatile("cp.async.wait_group 1;" ::: "memory")

// ================= fp32 -> fp16 conversion (inputs + weights) =================
__global__ __launch_bounds__(256) void to_half7(
    const float* __restrict__ s0, const float* __restrict__ s1, const float* __restrict__ s2,
    const float* __restrict__ s3, const float* __restrict__ s4, const float* __restrict__ s5,
    const float* __restrict__ s6,
    __half* __restrict__ d0, __half* __restrict__ d1, __half* __restrict__ d2,
    __half* __restrict__ d3, __half* __restrict__ d4, __half* __restrict__ d5,
    __half* __restrict__ d6)
{
    int b = blockIdx.x;
    const float* src; __half* dst; int off;
    if      (b < 2048) { src = s0; dst = d0; off = b; }
    else if (b < 4096) { src = s1; dst = d1; off = b - 2048; }
    else if (b < 6144) { src = s2; dst = d2; off = b - 4096; }
    else {
        int w = (b - 6144) >> 9;
        off = (b - 6144) & 511;
        src = (w == 0) ? s3 : (w == 1) ? s4 : (w == 2) ? s5 : s6;
        dst = (w == 0) ? d3 : (w == 1) ? d4 : (w == 2) ? d5 : d6;
    }
    size_t base = (size_t)off * 2048 + threadIdx.x * 8;
    float4 u0 = *(const float4*)(src + base);
    float4 u1 = *(const float4*)(src + base + 4);
    uint4 o;
    o.x = f2h2(u0.x, u0.y); o.y = f2h2(u0.z, u0.w);
    o.z = f2h2(u1.x, u1.y); o.w = f2h2(u1.z, u1.w);
    *(uint4*)(dst + base) = o;
}

// ============ core fp16 NT GEMM mainloop — cp.async 3-stage ============
template<int KDIM>
__device__ __forceinline__ void gemm_core_cp(
    const __half* __restrict__ Ag, const __half* __restrict__ Bg,
    uint32_t* __restrict__ As, uint32_t* __restrict__ Bs,
    int tid, int lane, int wm, int wn, float acc[4][4][4])
{
    const int arow = tid >> 1;
    const int kk4  = (tid & 1) * 4;
    const uint32_t a_sm = (uint32_t)__cvta_generic_to_shared(As) + (uint32_t)(arow * 48 + kk4 * 4);
    const uint32_t b_sm = (uint32_t)__cvta_generic_to_shared(Bs) + (uint32_t)(arow * 48 + kk4 * 4);
    const int NIT = KDIM / 16;

#pragma unroll
    for (int s = 0; s < 2; s++) {
        if (s < NIT) {
            CP_ASYNC16(a_sm + s * (128 * 48), Ag + s * 16);
            CP_ASYNC16(b_sm + s * (128 * 48), Bg + s * 16);
        }
        CP_COMMIT();
    }

    const int mg = wm * 64 + (lane >> 2);
    const int ng = wn * 32 + (lane >> 2);
    const int kl = lane & 3;

    int stage = 0;
    for (int it = 0; it < NIT; it++) {
        CP_WAIT1();
        __syncthreads();
        {
            int s2 = stage + 2; if (s2 >= 3) s2 -= 3;
            if (it + 2 < NIT) {
                CP_ASYNC16(a_sm + s2 * (128 * 48), Ag + (it + 2) * 16);
                CP_ASYNC16(b_sm + s2 * (128 * 48), Bg + (it + 2) * 16);
            }
            CP_COMMIT();
        }
        const uint32_t* Asb = As + stage * (128 * 12);
        const uint32_t* Bsb = Bs + stage * (128 * 12);
        uint32_t af[4][4];
#pragma unroll
        for (int i = 0; i < 4; i++) {
            af[i][0] = Asb[(mg + i * 16) * 12 + kl];
            af[i][1] = Asb[(mg + i * 16 + 8) * 12 + kl];
            af[i][2] = Asb[(mg + i * 16) * 12 + kl + 4];
            af[i][3] = Asb[(mg + i * 16 + 8) * 12 + kl + 4];
        }
        uint32_t bf[4][2];
#pragma unroll
        for (int j = 0; j < 4; j++) {
            bf[j][0] = Bsb[(ng + j * 8) * 12 + kl];
            bf[j][1] = Bsb[(ng + j * 8) * 12 + kl + 4];
        }
#pragma unroll
        for (int j = 0; j < 4; j++)
#pragma unroll
            for (int i = 0; i < 4; i++)
                mma_f16(acc[i][j], af[i][0], af[i][1], af[i][2], af[i][3],
                        bf[j][0], bf[j][1]);

        stage++; if (stage == 3) stage = 0;
    }
}

// ================= fused q/k/v projections =================
template<class TC>
__global__ __launch_bounds__(256, 2) void proj3_h(
    const __half* __restrict__ X0, const __half* __restrict__ X1, const __half* __restrict__ X2,
    const __half* __restrict__ W0, const __half* __restrict__ W1, const __half* __restrict__ W2,
    const float* __restrict__ bi0, const float* __restrict__ bi1, const float* __restrict__ bi2,
    TC* __restrict__ C0, TC* __restrict__ C1, TC* __restrict__ C2)
{
    constexpr bool OUT_HALF = std::is_same<TC, __half>::value;
    __shared__ __align__(16) uint32_t As[3 * 128 * 12];
    __shared__ __align__(16) uint32_t Bs[3 * 128 * 12];

    const int tid  = threadIdx.x;
    const int lane = tid & 31;
    const int wid  = tid >> 5;
    const int wm   = wid & 1;
    const int wn   = wid >> 1;
    const int bm   = blockIdx.y * 128;
    const int bn   = blockIdx.x * 128;
    const int z    = blockIdx.z;

    const __half* X    = (z == 0) ? X0 : (z == 1) ? X1 : X2;
    const __half* W    = (z == 0) ? W0 : (z == 1) ? W1 : W2;
    const float*  bias = (z == 0) ? bi0 : (z == 1) ? bi1 : bi2;
    TC*           C    = (z == 0) ? C0 : (z == 1) ? C1 : C2;

    const int arow = tid >> 1;
    const int ak   = (tid & 1) * 8;
    const __half* Ap = X + (size_t)(bm + arow) * D_ + ak;
    const __half* Bp = W + (size_t)(bn + arow) * D_ + ak;

    float acc[4][4][4];
#pragma unroll
    for (int i = 0; i < 4; i++)
#pragma unroll
        for (int j = 0; j < 4; j++)
#pragma unroll
            for (int e = 0; e < 4; e++) acc[i][j][e] = 0.f;

    gemm_core_cp<D_>(Ap, Bp, As, Bs, tid, lane, wm, wn, acc);

    const int rl   = wm * 64 + (lane >> 2);
    const int col0 = bn + wn * 32 + (lane & 3) * 2;
    float2 bvj[4];
#pragma unroll
    for (int j = 0; j < 4; j++)
        bvj[j] = *(const float2*)&bias[col0 + j * 8];

#pragma unroll
    for (int i = 0; i < 4; i++) {
#pragma unroll
        for (int j = 0; j < 4; j++) {
            const int r = bm + rl + i * 16;
            const int c = col0 + j * 8;
            float lx = acc[i][j][0] + bvj[j].x, ly = acc[i][j][1] + bvj[j].y;
            float hx = acc[i][j][2] + bvj[j].x, hy = acc[i][j][3] + bvj[j].y;
            if constexpr (OUT_HALF) {
                *(uint32_t*)&C[(size_t)r * D_ + c]       = f2h2(lx, ly);
                *(uint32_t*)&C[(size_t)(r + 8) * D_ + c] = f2h2(hx, hy);
            } else {
                float2 lo; lo.x = lx; lo.y = ly;
                float2 hi; hi.x = hx; hi.y = hy;
                *(float2*)&C[(size_t)r * D_ + c]       = lo;
                *(float2*)&C[(size_t)(r + 8) * D_ + c] = hi;
            }
        }
    }
}

// ================= QK^T -> exp fp16 scratch + partials =================
__global__ __launch_bounds__(256, 2) void qk_h(
    const __half* __restrict__ Q, const __half* __restrict__ K,
    __half* __restrict__ Pexp, float* __restrict__ partial)
{
    __shared__ __align__(16) uint32_t As[3 * 128 * 12];
    __shared__ __align__(16) uint32_t Bs[3 * 128 * 12];

    const int tid  = threadIdx.x;
    const int lane = tid & 31;
    const int wid  = tid >> 5;
    const int wm   = wid & 1;
    const int wn   = wid >> 1;
    const int bm   = blockIdx.y * 128;
    const int bn   = blockIdx.x * 128;
    const int z    = blockIdx.z;
    const int zb   = z >> 4, zh = z & 15;
    const size_t base = (size_t)zb * S_ * D_ + (size_t)zh * DK_;

    const int arow = tid >> 1;
    const int ak   = (tid & 1) * 8;
    const __half* Ap = Q + base + (size_t)(bm + arow) * D_ + ak;
    const __half* Bp = K + base + (size_t)(bn + arow) * D_ + ak;

    float acc[4][4][4];
#pragma unroll
    for (int i = 0; i < 4; i++)
#pragma unroll
        for (int j = 0; j < 4; j++)
#pragma unroll
            for (int e = 0; e < 4; e++) acc[i][j][e] = 0.f;

    gemm_core_cp<DK_>(Ap, Bp, As, Bs, tid, lane, wm, wn, acc);

    __half* Cp = Pexp + (size_t)z * S_ * S_;
    const int rl   = wm * 64 + (lane >> 2);
    const int col0 = bn + wn * 32 + (lane & 3) * 2;

#pragma unroll
    for (int i = 0; i < 4; i++) {
        const int rlo = bm + rl + i * 16;
        const int rhi = rlo + 8;
        float pl = 0.f, ph = 0.f;
#pragma unroll
        for (int j = 0; j < 4; j++) {
            float e0 = __expf(acc[i][j][0] * 0.125f);
            float e1 = __expf(acc[i][j][1] * 0.125f);
            float e2 = __expf(acc[i][j][2] * 0.125f);
            float e3 = __expf(acc[i][j][3] * 0.125f);
            __stcs((unsigned int*)&Cp[(size_t)rlo * S_ + col0 + j * 8], f2h2(e0, e1));
            __stcs((unsigned int*)&Cp[(size_t)rhi * S_ + col0 + j * 8], f2h2(e2, e3));
            pl += e0 + e1;
            ph += e2 + e3;
        }
        pl += __shfl_xor_sync(0xffffffffu, pl, 1);
        pl += __shfl_xor_sync(0xffffffffu, pl, 2);
        ph += __shfl_xor_sync(0xffffffffu, ph, 1);
        ph += __shfl_xor_sync(0xffffffffu, ph, 2);
        if ((lane & 3) == 0) {
            partial[((size_t)z * S_ + rlo) * 64 + blockIdx.x * 4 + wn] = pl;
            partial[((size_t)z * S_ + rhi) * 64 + blockIdx.x * 4 + wn] = ph;
        }
    }
}

// ================= PV: depth-3 register prefetch + streaming hints =================
__global__ __launch_bounds__(256, 2) void pv_h(
    const __half* __restrict__ Pexp, float* __restrict__ attn,
    const __half* __restrict__ Vg,
    __half* __restrict__ ctx, const float* __restrict__ partial)
{
    __shared__ uint32_t Ps[2][8][136];
    __shared__ uint32_t Vs[2][8][72];
    __shared__ float s_inv[128];

    const int tid  = threadIdx.x;
    const int lane = tid & 31;
    const int wid  = tid >> 5;
    const int wm   = wid & 3;
    const int wn   = wid >> 2;
    const int bm   = blockIdx.x * 128;
    const int z    = blockIdx.y;
    const int zb   = z >> 4, zh = z & 15;

    // prologue: per-row inverse sums (64 partials per row)
    {
        const int r = tid >> 1;
        const float* pp = partial + ((size_t)z * S_ + bm + r) * 64 + (tid & 1) * 32;
        float s = 0.f;
#pragma unroll
        for (int f = 0; f < 8; f++) {
            float4 u = ((const float4*)pp)[f];
            s += (u.x + u.y) + (u.z + u.w);
        }
        s += __shfl_xor_sync(0xffffffffu, s, 1);
        if (!(tid & 1)) s_inv[r] = 1.f / s;
    }
    __syncthreads();

    const int prow = tid >> 1;
    const int kkb  = (tid & 1) * 4;
    const __half* P = Pexp + (size_t)z * S_ * S_ + (size_t)(bm + prow) * S_ + (tid & 1) * 8;
    float* Aout = attn + (size_t)z * S_ * S_ + (size_t)(bm + prow) * S_ + (tid & 1) * 8;
    const float inv = s_inv[prow];

    const int vu = wid;
    const int vn = lane * 2;
    const __half* Vbase = Vg + (size_t)zb * S_ * D_ + (size_t)zh * DK_ + vn;

    float acc[2][4][4];
#pragma unroll
    for (int i = 0; i < 2; i++)
#pragma unroll
        for (int j = 0; j < 4; j++)
#pragma unroll
            for (int e = 0; e < 4; e++) acc[i][j][e] = 0.f;

    const int NIT = S_ / 16;

    // stage 0: load, write attn, STS
    {
        uint4 p0 = __ldcs((const uint4*)P);
        __half2 h0 = *(__half2*)&p0.x, h1 = *(__half2*)&p0.y;
        __half2 h2 = *(__half2*)&p0.z, h3 = *(__half2*)&p0.w;
        float4 o0, o1;
        o0.x = __low2float(h0) * inv;  o0.y = __high2float(h0) * inv;
        o0.z = __low2float(h1) * inv;  o0.w = __high2float(h1) * inv;
        o1.x = __low2float(h2) * inv;  o1.y = __high2float(h2) * inv;
        o1.z = __low2float(h3) * inv;  o1.w = __high2float(h3) * inv;
        __stcs((float4*)(Aout), o0);
        __stcs((float4*)(Aout + 4), o1);
        __half2 e0 = *(const __half2*)(Vbase + (size_t)(2 * vu) * D_);
        __half2 e1 = *(const __half2*)(Vbase + (size_t)(2 * vu + 1) * D_);
        STS8HU(Ps[0], kkb, prow, p0);
        __half2 w0 = __lows2half2(e0, e1);
        __half2 w1 = __highs2half2(e0, e1);
        Vs[0][vu][vn]     = *(uint32_t*)&w0;
        Vs[0][vu][vn + 1] = *(uint32_t*)&w1;
    }
    // register pipeline: A = it+1, B = it+2, C = it+3
    uint4 phA, phB, phC;
    __half2 veA, voA, veB, voB, veC, voC;
    phA = __ldcs((const uint4*)(P + 16));
    veA = *(const __half2*)(Vbase + (size_t)(16 + 2 * vu) * D_);
    voA = *(const __half2*)(Vbase + (size_t)(16 + 2 * vu + 1) * D_);
    phB = __ldcs((const uint4*)(P + 32));
    veB = *(const __half2*)(Vbase + (size_t)(32 + 2 * vu) * D_);
    voB = *(const __half2*)(Vbase + (size_t)(32 + 2 * vu + 1) * D_);
    __syncthreads();

    const int mg = wm * 32 + (lane >> 2);
    const int ng = wn * 32 + (lane >> 2);
    const int kl = lane & 3;

#pragma unroll 2
    for (int it = 0; it < NIT; it++) {
        const int cur = it & 1;
        // prefetch it+3 into regs C
        if (it + 3 < NIT) {
            const int k0 = (it + 3) * 16;
            phC = __ldcs((const uint4*)(P + k0));
            veC = *(const __half2*)(Vbase + (size_t)(k0 + 2 * vu) * D_);
            voC = *(const __half2*)(Vbase + (size_t)(k0 + 2 * vu + 1) * D_);
        }
        // compute current stage
        {
            uint32_t af[2][4];
#pragma unroll
            for (int i = 0; i < 2; i++) {
                af[i][0] = Ps[cur][kl    ][mg + i * 16];
                af[i][1] = Ps[cur][kl    ][mg + i * 16 + 8];
                af[i][2] = Ps[cur][kl + 4][mg + i * 16];
                af[i][3] = Ps[cur][kl + 4][mg + i * 16 + 8];
            }
            uint32_t bf[4][2];
#pragma unroll
            for (int j = 0; j < 4; j++) {
                bf[j][0] = Vs[cur][kl    ][ng + j * 8];
                bf[j][1] = Vs[cur][kl + 4][ng + j * 8];
            }
#pragma unroll
            for (int j = 0; j < 4; j++)
#pragma unroll
                for (int i = 0; i < 2; i++)
                    mma_f16(acc[i][j], af[i][0], af[i][1], af[i][2], af[i][3],
                            bf[j][0], bf[j][1]);
        }
        if (it + 1 < NIT) {
            const int k1 = (it + 1) * 16;
            // attn write for it+1 from regs A
            __half2 h0 = *(__half2*)&phA.x, h1 = *(__half2*)&phA.y;
            __half2 h2 = *(__half2*)&phA.z, h3 = *(__half2*)&phA.w;
            float4 o0, o1;
            o0.x = __low2float(h0) * inv;  o0.y = __high2float(h0) * inv;
            o0.z = __low2float(h1) * inv;  o0.w = __high2float(h1) * inv;
            o1.x = __low2float(h2) * inv;  o1.y = __high2float(h2) * inv;
            o1.z = __low2float(h3) * inv;  o1.w = __high2float(h3) * inv;
            __stcs((float4*)(Aout + k1), o0);
            __stcs((float4*)(Aout + k1 + 4), o1);
            STS8HU(Ps[cur ^ 1], kkb, prow, phA);
            __half2 w0 = __lows2half2(veA, voA);
            __half2 w1 = __highs2half2(veA, voA);
            Vs[cur ^ 1][vu][vn]     = *(uint32_t*)&w0;
            Vs[cur ^ 1][vu][vn + 1] = *(uint32_t*)&w1;
            __syncthreads();
        }
        phA = phB; veA = veB; voA = voB;
        phB = phC; veB = veC; voB = voC;
    }

    __half* Cc = ctx + (size_t)zb * S_ * D_ + (size_t)zh * DK_;
    const int row0 = bm + wm * 32 + (lane >> 2);
    const int col0 = wn * 32 + (lane & 3) * 2;
#pragma unroll
    for (int i = 0; i < 2; i++) {
        const float ilo = s_inv[wm * 32 + (lane >> 2) + i * 16];
        const float ihi = s_inv[wm * 32 + (lane >> 2) + i * 16 + 8];
#pragma unroll
        for (int j = 0; j < 4; j++) {
            const int r = row0 + i * 16;
            const int c = col0 + j * 8;
            *(uint32_t*)&Cc[(size_t)r * D_ + c]       = f2h2(acc[i][j][0] * ilo, acc[i][j][1] * ilo);
            *(uint32_t*)&Cc[(size_t)(r + 8) * D_ + c] = f2h2(acc[i][j][2] * ihi, acc[i][j][3] * ihi);
        }
    }
}

// ---------------- launch ----------------
extern "C" void kernel_launch(void* const* d_in, const int* in_sizes, int n_in,
                              void* d_out, int out_size)
{
    const float* query = (const float*)d_in[0];
    const float* key   = (const float*)d_in[1];
    const float* value = (const float*)d_in[2];
    const float* Wq    = (const float*)d_in[3];
    const float* bq    = (const float*)d_in[4];
    const float* Wk    = (const float*)d_in[5];
    const float* bk    = (const float*)d_in[6];
    const float* Wv    = (const float*)d_in[7];
    const float* bv    = (const float*)d_in[8];
    const float* Wo    = (const float*)d_in[9];
    const float* bo    = (const float*)d_in[10];

    float* out  = (float*)d_out;                          // (B,S,D)
    float* attn = out + (size_t)B_ * S_ * D_;             // (B,H,S,S)

    __half *qh, *kh, *vh, *ctxh, *xq, *xk, *xv, *wq, *wk, *wv, *wo, *ph;
    float *part;
    cudaGetSymbolAddress((void**)&qh,   g_qh);
    cudaGetSymbolAddress((void**)&kh,   g_kh);
    cudaGetSymbolAddress((void**)&vh,   g_vh);
    cudaGetSymbolAddress((void**)&ctxh, g_ctxh);
    cudaGetSymbolAddress((void**)&xq,   g_xq);
    cudaGetSymbolAddress((void**)&xk,   g_xk);
    cudaGetSymbolAddress((void**)&xv,   g_xv);
    cudaGetSymbolAddress((void**)&wq,   g_wq);
    cudaGetSymbolAddress((void**)&wk,   g_wk);
    cudaGetSymbolAddress((void**)&wv,   g_wv);
    cudaGetSymbolAddress((void**)&wo,   g_wo);
    cudaGetSymbolAddress((void**)&ph,   g_ph);
    cudaGetSymbolAddress((void**)&part, g_partial);

    // 0) convert inputs + weights to fp16 once
    to_half7<<<8192, 256>>>(query, key, value, Wq, Wk, Wv, Wo,
                            xq, xk, xv, wq, wk, wv, wo);

    // 1) fused q/k/v projections (grid.z = 3)
    dim3 pgrid(D_ / 128, (B_ * S_) / 128, 3);
    proj3_h<__half><<<pgrid, 256>>>(xq, xk, xv, wq, wk, wv, bq, bk, bv, qh, kh, vh);

    // 2) QK^T -> exp fp16 scratch + partials
    dim3 qkgrid(S_ / 128, S_ / 128, B_ * H_);
    qk_h<<<qkgrid, 256>>>(qh, kh, ph, part);

    // 3) normalized attn write + ctx = inv * (expP @ V)
    dim3 pvgrid(S_ / 128, B_ * H_);
    pv_h<<<pvgrid, 256>>>(ph, attn, vh, ctxh, part);

    // 4) output projection (fp16 x fp16 -> fp32)
    dim3 ogrid(D_ / 128, (B_ * S_) / 128, 1);
    proj3_h<float><<<ogrid, 256>>>(ctxh, ctxh, ctxh, wo, wo, wo, bo, bo, bo, out, out, out);
}

// round 16
// speedup vs baseline: 1.0480x; 1.0385x over previous
#include <cuda_runtime.h>
#include <cuda_fp16.h>
#include <math.h>
#include <stdint.h>
#include <type_traits>

// Problem constants
#define B_ 2
#define S_ 2048
#define D_ 1024
#define H_ 16
#define DK_ 64

// ---------------- scratch (no cudaMalloc allowed) ----------------
__device__ __half g_qh[(size_t)B_ * S_ * D_];
__device__ __half g_kh[(size_t)B_ * S_ * D_];
__device__ __half g_vh[(size_t)B_ * S_ * D_];
__device__ __half g_ctxh[(size_t)B_ * S_ * D_];
// fp16 copies of inputs / weights
__device__ __half g_xq[(size_t)B_ * S_ * D_];
__device__ __half g_xk[(size_t)B_ * S_ * D_];
__device__ __half g_xv[(size_t)B_ * S_ * D_];
__device__ __half g_wq[(size_t)D_ * D_];
__device__ __half g_wk[(size_t)D_ * D_];
__device__ __half g_wv[(size_t)D_ * D_];
__device__ __half g_wo[(size_t)D_ * D_];
// fp16 exp(scores) scratch
__device__ __half g_ph[(size_t)B_ * H_ * S_ * S_];
// per-row exp partial sums: [z][row][16 bn-tiles * 4 wn] = 64 partials/row
__device__ float g_partial[(size_t)B_ * H_ * S_ * 64];

// ---------------- FP16 helpers ----------------
__device__ __forceinline__ uint32_t f2h2(float lo, float hi) {
    __half2 h = __floats2half2_rn(lo, hi);
    return *(uint32_t*)&h;
}

__device__ __forceinline__ void mma_f16(float c[4],
    uint32_t a0, uint32_t a1, uint32_t a2, uint32_t a3,
    uint32_t b0, uint32_t b1)
{
    asm volatile(
        "mma.sync.aligned.m16n8k16.row.col.f32.f16.f16.f32 "
        "{%0,%1,%2,%3}, {%4,%5,%6,%7}, {%8,%9}, {%0,%1,%2,%3};"
        : "+f"(c[0]), "+f"(c[1]), "+f"(c[2]), "+f"(c[3])
        : "r"(a0), "r"(a1), "r"(a2), "r"(a3), "r"(b0), "r"(b1));
}

#define STS8HU(s, kkb, r, u) do { \
    (s)[(kkb) + 0][r] = (u).x; \
    (s)[(kkb) + 1][r] = (u).y; \
    (s)[(kkb) + 2][r] = (u).z; \
    (s)[(kkb) + 3][r] = (u).w; \
} while (0)

// ---------------- cp.async helpers ----------------
#define CP_ASYNC16(saddr, gptr) \
    asm volatile("cp.async.cg.shared.global [%0], [%1], 16;" \
                 :: "r"(saddr), "l"(gptr) : "memory")
#define CP_COMMIT() asm volatile("cp.async.commit_group;" ::: "memory")
#define CP_WAIT1()  asm volatile("cp.async.wait_group 1;" ::: "memory")

// ================= fp32 -> fp16 conversion (inputs + weights) =================
__global__ __launch_bounds__(256) void to_half7(
    const float* __restrict__ s0, const float* __restrict__ s1, const float* __restrict__ s2,
    const float* __restrict__ s3, const float* __restrict__ s4, const float* __restrict__ s5,
    const float* __restrict__ s6,
    __half* __restrict__ d0, __half* __restrict__ d1, __half* __restrict__ d2,
    __half* __restrict__ d3, __half* __restrict__ d4, __half* __restrict__ d5,
    __half* __restrict__ d6)
{
    int b = blockIdx.x;
    const float* src; __half* dst; int off;
    if      (b < 2048) { src = s0; dst = d0; off = b; }
    else if (b < 4096) { src = s1; dst = d1; off = b - 2048; }
    else if (b < 6144) { src = s2; dst = d2; off = b - 4096; }
    else {
        int w = (b - 6144) >> 9;
        off = (b - 6144) & 511;
        src = (w == 0) ? s3 : (w == 1) ? s4 : (w == 2) ? s5 : s6;
        dst = (w == 0) ? d3 : (w == 1) ? d4 : (w == 2) ? d5 : d6;
    }
    size_t base = (size_t)off * 2048 + threadIdx.x * 8;
    float4 u0 = *(const float4*)(src + base);
    float4 u1 = *(const float4*)(src + base + 4);
    uint4 o;
    o.x = f2h2(u0.x, u0.y); o.y = f2h2(u0.z, u0.w);
    o.z = f2h2(u1.x, u1.y); o.w = f2h2(u1.z, u1.w);
    *(uint4*)(dst + base) = o;
}

// ============ core fp16 NT GEMM mainloop — cp.async 3-stage ============
template<int KDIM>
__device__ __forceinline__ void gemm_core_cp(
    const __half* __restrict__ Ag, const __half* __restrict__ Bg,
    uint32_t* __restrict__ As, uint32_t* __restrict__ Bs,
    int tid, int lane, int wm, int wn, float acc[4][4][4])
{
    const int arow = tid >> 1;
    const int kk4  = (tid & 1) * 4;
    const uint32_t a_sm = (uint32_t)__cvta_generic_to_shared(As) + (uint32_t)(arow * 48 + kk4 * 4);
    const uint32_t b_sm = (uint32_t)__cvta_generic_to_shared(Bs) + (uint32_t)(arow * 48 + kk4 * 4);
    const int NIT = KDIM / 16;

#pragma unroll
    for (int s = 0; s < 2; s++) {
        if (s < NIT) {
            CP_ASYNC16(a_sm + s * (128 * 48), Ag + s * 16);
            CP_ASYNC16(b_sm + s * (128 * 48), Bg + s * 16);
        }
        CP_COMMIT();
    }

    const int mg = wm * 64 + (lane >> 2);
    const int ng = wn * 32 + (lane >> 2);
    const int kl = lane & 3;

    int stage = 0;
    for (int it = 0; it < NIT; it++) {
        CP_WAIT1();
        __syncthreads();
        {
            int s2 = stage + 2; if (s2 >= 3) s2 -= 3;
            if (it + 2 < NIT) {
                CP_ASYNC16(a_sm + s2 * (128 * 48), Ag + (it + 2) * 16);
                CP_ASYNC16(b_sm + s2 * (128 * 48), Bg + (it + 2) * 16);
            }
            CP_COMMIT();
        }
        const uint32_t* Asb = As + stage * (128 * 12);
        const uint32_t* Bsb = Bs + stage * (128 * 12);
        uint32_t af[4][4];
#pragma unroll
        for (int i = 0; i < 4; i++) {
            af[i][0] = Asb[(mg + i * 16) * 12 + kl];
            af[i][1] = Asb[(mg + i * 16 + 8) * 12 + kl];
            af[i][2] = Asb[(mg + i * 16) * 12 + kl + 4];
            af[i][3] = Asb[(mg + i * 16 + 8) * 12 + kl + 4];
        }
        uint32_t bf[4][2];
#pragma unroll
        for (int j = 0; j < 4; j++) {
            bf[j][0] = Bsb[(ng + j * 8) * 12 + kl];
            bf[j][1] = Bsb[(ng + j * 8) * 12 + kl + 4];
        }
#pragma unroll
        for (int j = 0; j < 4; j++)
#pragma unroll
            for (int i = 0; i < 4; i++)
                mma_f16(acc[i][j], af[i][0], af[i][1], af[i][2], af[i][3],
                        bf[j][0], bf[j][1]);

        stage++; if (stage == 3) stage = 0;
    }
}

// ================= fused q/k/v projections =================
template<class TC>
__global__ __launch_bounds__(256, 2) void proj3_h(
    const __half* __restrict__ X0, const __half* __restrict__ X1, const __half* __restrict__ X2,
    const __half* __restrict__ W0, const __half* __restrict__ W1, const __half* __restrict__ W2,
    const float* __restrict__ bi0, const float* __restrict__ bi1, const float* __restrict__ bi2,
    TC* __restrict__ C0, TC* __restrict__ C1, TC* __restrict__ C2)
{
    constexpr bool OUT_HALF = std::is_same<TC, __half>::value;
    __shared__ __align__(16) uint32_t As[3 * 128 * 12];
    __shared__ __align__(16) uint32_t Bs[3 * 128 * 12];

    const int tid  = threadIdx.x;
    const int lane = tid & 31;
    const int wid  = tid >> 5;
    const int wm   = wid & 1;
    const int wn   = wid >> 1;
    const int bm   = blockIdx.y * 128;
    const int bn   = blockIdx.x * 128;
    const int z    = blockIdx.z;

    const __half* X    = (z == 0) ? X0 : (z == 1) ? X1 : X2;
    const __half* W    = (z == 0) ? W0 : (z == 1) ? W1 : W2;
    const float*  bias = (z == 0) ? bi0 : (z == 1) ? bi1 : bi2;
    TC*           C    = (z == 0) ? C0 : (z == 1) ? C1 : C2;

    const int arow = tid >> 1;
    const int ak   = (tid & 1) * 8;
    const __half* Ap = X + (size_t)(bm + arow) * D_ + ak;
    const __half* Bp = W + (size_t)(bn + arow) * D_ + ak;

    float acc[4][4][4];
#pragma unroll
    for (int i = 0; i < 4; i++)
#pragma unroll
        for (int j = 0; j < 4; j++)
#pragma unroll
            for (int e = 0; e < 4; e++) acc[i][j][e] = 0.f;

    gemm_core_cp<D_>(Ap, Bp, As, Bs, tid, lane, wm, wn, acc);

    const int rl   = wm * 64 + (lane >> 2);
    const int col0 = bn + wn * 32 + (lane & 3) * 2;
    float2 bvj[4];
#pragma unroll
    for (int j = 0; j < 4; j++)
        bvj[j] = *(const float2*)&bias[col0 + j * 8];

#pragma unroll
    for (int i = 0; i < 4; i++) {
#pragma unroll
        for (int j = 0; j < 4; j++) {
            const int r = bm + rl + i * 16;
            const int c = col0 + j * 8;
            float lx = acc[i][j][0] + bvj[j].x, ly = acc[i][j][1] + bvj[j].y;
            float hx = acc[i][j][2] + bvj[j].x, hy = acc[i][j][3] + bvj[j].y;
            if constexpr (OUT_HALF) {
                *(uint32_t*)&C[(size_t)r * D_ + c]       = f2h2(lx, ly);
                *(uint32_t*)&C[(size_t)(r + 8) * D_ + c] = f2h2(hx, hy);
            } else {
                float2 lo; lo.x = lx; lo.y = ly;
                float2 hi; hi.x = hx; hi.y = hy;
                *(float2*)&C[(size_t)r * D_ + c]       = lo;
                *(float2*)&C[(size_t)(r + 8) * D_ + c] = hi;
            }
        }
    }
}

// ================= QK^T -> exp fp16 scratch + partials =================
__global__ __launch_bounds__(256, 2) void qk_h(
    const __half* __restrict__ Q, const __half* __restrict__ K,
    __half* __restrict__ Pexp, float* __restrict__ partial)
{
    __shared__ __align__(16) uint32_t As[3 * 128 * 12];
    __shared__ __align__(16) uint32_t Bs[3 * 128 * 12];

    const int tid  = threadIdx.x;
    const int lane = tid & 31;
    const int wid  = tid >> 5;
    const int wm   = wid & 1;
    const int wn   = wid >> 1;
    const int bm   = blockIdx.y * 128;
    const int bn   = blockIdx.x * 128;
    const int z    = blockIdx.z;
    const int zb   = z >> 4, zh = z & 15;
    const size_t base = (size_t)zb * S_ * D_ + (size_t)zh * DK_;

    const int arow = tid >> 1;
    const int ak   = (tid & 1) * 8;
    const __half* Ap = Q + base + (size_t)(bm + arow) * D_ + ak;
    const __half* Bp = K + base + (size_t)(bn + arow) * D_ + ak;

    float acc[4][4][4];
#pragma unroll
    for (int i = 0; i < 4; i++)
#pragma unroll
        for (int j = 0; j < 4; j++)
#pragma unroll
            for (int e = 0; e < 4; e++) acc[i][j][e] = 0.f;

    gemm_core_cp<DK_>(Ap, Bp, As, Bs, tid, lane, wm, wn, acc);

    __half* Cp = Pexp + (size_t)z * S_ * S_;
    const int rl   = wm * 64 + (lane >> 2);
    const int col0 = bn + wn * 32 + (lane & 3) * 2;

#pragma unroll
    for (int i = 0; i < 4; i++) {
        const int rlo = bm + rl + i * 16;
        const int rhi = rlo + 8;
        float pl = 0.f, ph = 0.f;
#pragma unroll
        for (int j = 0; j < 4; j++) {
            float e0 = __expf(acc[i][j][0] * 0.125f);
            float e1 = __expf(acc[i][j][1] * 0.125f);
            float e2 = __expf(acc[i][j][2] * 0.125f);
            float e3 = __expf(acc[i][j][3] * 0.125f);
            *(uint32_t*)&Cp[(size_t)rlo * S_ + col0 + j * 8] = f2h2(e0, e1);
            *(uint32_t*)&Cp[(size_t)rhi * S_ + col0 + j * 8] = f2h2(e2, e3);
            pl += e0 + e1;
            ph += e2 + e3;
        }
        pl += __shfl_xor_sync(0xffffffffu, pl, 1);
        pl += __shfl_xor_sync(0xffffffffu, pl, 2);
        ph += __shfl_xor_sync(0xffffffffu, ph, 1);
        ph += __shfl_xor_sync(0xffffffffu, ph, 2);
        if ((lane & 3) == 0) {
            partial[((size_t)z * S_ + rlo) * 64 + blockIdx.x * 4 + wn] = pl;
            partial[((size_t)z * S_ + rhi) * 64 + blockIdx.x * 4 + wn] = ph;
        }
    }
}

// ================= PV: BK=32, depth-1 (32k window) register prefetch =================
// Per iteration: 32 k, one barrier, 2x uint4 P loads + 4x half2 V loads in flight.
__global__ __launch_bounds__(256, 2) void pv_h(
    const __half* __restrict__ Pexp, float* __restrict__ attn,
    const __half* __restrict__ Vg,
    __half* __restrict__ ctx, const float* __restrict__ partial)
{
    __shared__ uint32_t Ps[2][16][136];
    __shared__ uint32_t Vs[2][16][72];
    __shared__ float s_inv[128];

    const int tid  = threadIdx.x;
    const int lane = tid & 31;
    const int wid  = tid >> 5;
    const int wm   = wid & 3;
    const int wn   = wid >> 2;
    const int bm   = blockIdx.x * 128;
    const int z    = blockIdx.y;
    const int zb   = z >> 4, zh = z & 15;

    // prologue: per-row inverse sums (64 partials per row)
    {
        const int r = tid >> 1;
        const float* pp = partial + ((size_t)z * S_ + bm + r) * 64 + (tid & 1) * 32;
        float s = 0.f;
#pragma unroll
        for (int f = 0; f < 8; f++) {
            float4 u = ((const float4*)pp)[f];
            s += (u.x + u.y) + (u.z + u.w);
        }
        s += __shfl_xor_sync(0xffffffffu, s, 1);
        if (!(tid & 1)) s_inv[r] = 1.f / s;
    }
    __syncthreads();

    const int prow = tid >> 1;
    const int kkb  = (tid & 1) * 8;      // kpair offset within 16-kpair tile
    const __half* P = Pexp + (size_t)z * S_ * S_ + (size_t)(bm + prow) * S_ + (tid & 1) * 16;
    float* Aout = attn + (size_t)z * S_ * S_ + (size_t)(bm + prow) * S_ + (tid & 1) * 16;
    const float inv = s_inv[prow];

    const int vu = wid;                  // warp covers V rows 4vu..4vu+3 per tile
    const int vn = lane * 2;
    const __half* Vbase = Vg + (size_t)zb * S_ * D_ + (size_t)zh * DK_ + vn;

    float acc[2][4][4];
#pragma unroll
    for (int i = 0; i < 2; i++)
#pragma unroll
        for (int j = 0; j < 4; j++)
#pragma unroll
            for (int e = 0; e < 4; e++) acc[i][j][e] = 0.f;

    const int NIT = S_ / 32;   // 64 iterations

    // helper lambdas expressed inline:
    // stage 0: load tile 0, write attn, STS
    {
        uint4 p0 = *(const uint4*)(P);
        uint4 p1 = *(const uint4*)(P + 8);
        __half2 h0, h1; float4 o;
        h0 = *(__half2*)&p0.x; h1 = *(__half2*)&p0.y;
        o.x = __low2float(h0) * inv; o.y = __high2float(h0) * inv;
        o.z = __low2float(h1) * inv; o.w = __high2float(h1) * inv;
        *(float4*)(Aout) = o;
        h0 = *(__half2*)&p0.z; h1 = *(__half2*)&p0.w;
        o.x = __low2float(h0) * inv; o.y = __high2float(h0) * inv;
        o.z = __low2float(h1) * inv; o.w = __high2float(h1) * inv;
        *(float4*)(Aout + 4) = o;
        h0 = *(__half2*)&p1.x; h1 = *(__half2*)&p1.y;
        o.x = __low2float(h0) * inv; o.y = __high2float(h0) * inv;
        o.z = __low2float(h1) * inv; o.w = __high2float(h1) * inv;
        *(float4*)(Aout + 8) = o;
        h0 = *(__half2*)&p1.z; h1 = *(__half2*)&p1.w;
        o.x = __low2float(h0) * inv; o.y = __high2float(h0) * inv;
        o.z = __low2float(h1) * inv; o.w = __high2float(h1) * inv;
        *(float4*)(Aout + 12) = o;

        STS8HU(Ps[0], kkb, prow, p0);
        STS8HU(Ps[0], kkb + 4, prow, p1);

        __half2 e0 = *(const __half2*)(Vbase + (size_t)(4 * vu) * D_);
        __half2 e1 = *(const __half2*)(Vbase + (size_t)(4 * vu + 1) * D_);
        __half2 e2 = *(const __half2*)(Vbase + (size_t)(4 * vu + 2) * D_);
        __half2 e3 = *(const __half2*)(Vbase + (size_t)(4 * vu + 3) * D_);
        __half2 w0 = __lows2half2(e0, e1), w1 = __highs2half2(e0, e1);
        __half2 w2 = __lows2half2(e2, e3), w3 = __highs2half2(e2, e3);
        Vs[0][2 * vu][vn]         = *(uint32_t*)&w0;
        Vs[0][2 * vu][vn + 1]     = *(uint32_t*)&w1;
        Vs[0][2 * vu + 1][vn]     = *(uint32_t*)&w2;
        Vs[0][2 * vu + 1][vn + 1] = *(uint32_t*)&w3;
    }
    __syncthreads();

    const int mg = wm * 32 + (lane >> 2);
    const int ng = wn * 32 + (lane >> 2);
    const int kl = lane & 3;

    uint4 qA, qB;
    __half2 fA, fB, fC, fD;

    for (int it = 0; it < NIT; it++) {
        const int cur = it & 1;
        // prefetch tile it+1 (32 k ahead)
        if (it + 1 < NIT) {
            const int k0 = (it + 1) * 32;
            qA = *(const uint4*)(P + k0);
            qB = *(const uint4*)(P + k0 + 8);
            fA = *(const __half2*)(Vbase + (size_t)(k0 + 4 * vu) * D_);
            fB = *(const __half2*)(Vbase + (size_t)(k0 + 4 * vu + 1) * D_);
            fC = *(const __half2*)(Vbase + (size_t)(k0 + 4 * vu + 2) * D_);
            fD = *(const __half2*)(Vbase + (size_t)(k0 + 4 * vu + 3) * D_);
        }
        // compute on current tile: 2 k16 sub-steps
#pragma unroll
        for (int s = 0; s < 2; s++) {
            const int kb = s * 8 + kl;
            uint32_t af[2][4];
#pragma unroll
            for (int i = 0; i < 2; i++) {
                af[i][0] = Ps[cur][kb    ][mg + i * 16];
                af[i][1] = Ps[cur][kb    ][mg + i * 16 + 8];
                af[i][2] = Ps[cur][kb + 4][mg + i * 16];
                af[i][3] = Ps[cur][kb + 4][mg + i * 16 + 8];
            }
            uint32_t bf[4][2];
#pragma unroll
            for (int j = 0; j < 4; j++) {
                bf[j][0] = Vs[cur][kb    ][ng + j * 8];
                bf[j][1] = Vs[cur][kb + 4][ng + j * 8];
            }
#pragma unroll
            for (int j = 0; j < 4; j++)
#pragma unroll
                for (int i = 0; i < 2; i++)
                    mma_f16(acc[i][j], af[i][0], af[i][1], af[i][2], af[i][3],
                            bf[j][0], bf[j][1]);
        }
        if (it + 1 < NIT) {
            const int k1 = (it + 1) * 32;
            // attn write for it+1 from prefetched regs
            __half2 h0, h1; float4 o;
            h0 = *(__half2*)&qA.x; h1 = *(__half2*)&qA.y;
            o.x = __low2float(h0) * inv; o.y = __high2float(h0) * inv;
            o.z = __low2float(h1) * inv; o.w = __high2float(h1) * inv;
            *(float4*)(Aout + k1) = o;
            h0 = *(__half2*)&qA.z; h1 = *(__half2*)&qA.w;
            o.x = __low2float(h0) * inv; o.y = __high2float(h0) * inv;
            o.z = __low2float(h1) * inv; o.w = __high2float(h1) * inv;
            *(float4*)(Aout + k1 + 4) = o;
            h0 = *(__half2*)&qB.x; h1 = *(__half2*)&qB.y;
            o.x = __low2float(h0) * inv; o.y = __high2float(h0) * inv;
            o.z = __low2float(h1) * inv; o.w = __high2float(h1) * inv;
            *(float4*)(Aout + k1 + 8) = o;
            h0 = *(__half2*)&qB.z; h1 = *(__half2*)&qB.w;
            o.x = __low2float(h0) * inv; o.y = __high2float(h0) * inv;
            o.z = __low2float(h1) * inv; o.w = __high2float(h1) * inv;
            *(float4*)(Aout + k1 + 12) = o;

            STS8HU(Ps[cur ^ 1], kkb, prow, qA);
            STS8HU(Ps[cur ^ 1], kkb + 4, prow, qB);

            __half2 w0 = __lows2half2(fA, fB), w1 = __highs2half2(fA, fB);
            __half2 w2 = __lows2half2(fC, fD), w3 = __highs2half2(fC, fD);
            Vs[cur ^ 1][2 * vu][vn]         = *(uint32_t*)&w0;
            Vs[cur ^ 1][2 * vu][vn + 1]     = *(uint32_t*)&w1;
            Vs[cur ^ 1][2 * vu + 1][vn]     = *(uint32_t*)&w2;
            Vs[cur ^ 1][2 * vu + 1][vn + 1] = *(uint32_t*)&w3;
            __syncthreads();
        }
    }

    __half* Cc = ctx + (size_t)zb * S_ * D_ + (size_t)zh * DK_;
    const int row0 = bm + wm * 32 + (lane >> 2);
    const int col0 = wn * 32 + (lane & 3) * 2;
#pragma unroll
    for (int i = 0; i < 2; i++) {
        const float ilo = s_inv[wm * 32 + (lane >> 2) + i * 16];
        const float ihi = s_inv[wm * 32 + (lane >> 2) + i * 16 + 8];
#pragma unroll
        for (int j = 0; j < 4; j++) {
            const int r = row0 + i * 16;
            const int c = col0 + j * 8;
            *(uint32_t*)&Cc[(size_t)r * D_ + c]       = f2h2(acc[i][j][0] * ilo, acc[i][j][1] * ilo);
            *(uint32_t*)&Cc[(size_t)(r + 8) * D_ + c] = f2h2(acc[i][j][2] * ihi, acc[i][j][3] * ihi);
        }
    }
}

// ---------------- launch ----------------
extern "C" void kernel_launch(void* const* d_in, const int* in_sizes, int n_in,
                              void* d_out, int out_size)
{
    const float* query = (const float*)d_in[0];
    const float* key   = (const float*)d_in[1];
    const float* value = (const float*)d_in[2];
    const float* Wq    = (const float*)d_in[3];
    const float* bq    = (const float*)d_in[4];
    const float* Wk    = (const float*)d_in[5];
    const float* bk    = (const float*)d_in[6];
    const float* Wv    = (const float*)d_in[7];
    const float* bv    = (const float*)d_in[8];
    const float* Wo    = (const float*)d_in[9];
    const float* bo    = (const float*)d_in[10];

    float* out  = (float*)d_out;                          // (B,S,D)
    float* attn = out + (size_t)B_ * S_ * D_;             // (B,H,S,S)

    __half *qh, *kh, *vh, *ctxh, *xq, *xk, *xv, *wq, *wk, *wv, *wo, *ph;
    float *part;
    cudaGetSymbolAddress((void**)&qh,   g_qh);
    cudaGetSymbolAddress((void**)&kh,   g_kh);
    cudaGetSymbolAddress((void**)&vh,   g_vh);
    cudaGetSymbolAddress((void**)&ctxh, g_ctxh);
    cudaGetSymbolAddress((void**)&xq,   g_xq);
    cudaGetSymbolAddress((void**)&xk,   g_xk);
    cudaGetSymbolAddress((void**)&xv,   g_xv);
    cudaGetSymbolAddress((void**)&wq,   g_wq);
    cudaGetSymbolAddress((void**)&wk,   g_wk);
    cudaGetSymbolAddress((void**)&wv,   g_wv);
    cudaGetSymbolAddress((void**)&wo,   g_wo);
    cudaGetSymbolAddress((void**)&ph,   g_ph);
    cudaGetSymbolAddress((void**)&part, g_partial);

    // 0) convert inputs + weights to fp16 once
    to_half7<<<8192, 256>>>(query, key, value, Wq, Wk, Wv, Wo,
                            xq, xk, xv, wq, wk, wv, wo);

    // 1) fused q/k/v projections (grid.z = 3)
    dim3 pgrid(D_ / 128, (B_ * S_) / 128, 3);
    proj3_h<__half><<<pgrid, 256>>>(xq, xk, xv, wq, wk, wv, bq, bk, bv, qh, kh, vh);

    // 2) QK^T -> exp fp16 scratch + partials
    dim3 qkgrid(S_ / 128, S_ / 128, B_ * H_);
    qk_h<<<qkgrid, 256>>>(qh, kh, ph, part);

    // 3) normalized attn write + ctx = inv * (expP @ V)
    dim3 pvgrid(S_ / 128, B_ * H_);
    pv_h<<<pvgrid, 256>>>(ph, attn, vh, ctxh, part);

    // 4) output projection (fp16 x fp16 -> fp32)
    dim3 ogrid(D_ / 128, (B_ * S_) / 128, 1);
    proj3_h<float><<<ogrid, 256>>>(ctxh, ctxh, ctxh, wo, wo, wo, bo, bo, bo, out, out, out);
}